// round 1
// baseline (speedup 1.0000x reference)
#include <cuda_runtime.h>
#include <math.h>

#define SEQ 256
#define NB 64
#define HID 300
#define G4 1200
#define NTAG 12

// recurrence config: 60 CTAs per direction, each owns 5 hidden units (20 gate rows)
#define R_CTAS 60
#define R_UPC 5
#define R_ROWS 20
#define R_KS 5
#define R_KCH 60
#define R_THREADS 320

// input-projection config: 20 CTAs of 60 gate rows cover the 1200 rows
#define IP_MB 20
#define IP_UPC 15
#define IP_ROWS 60

// ---------------- scratch (device globals; no allocations) ----------------
__device__ float g_XT[SEQ * HID * NB];          // x transposed per step: [s][k][b]
__device__ float g_G[2][SEQ][G4 * NB];          // input projections + bias: [d][s][row][b]
__device__ float g_hall[2][SEQ][HID * NB];      // hidden states: [d][s][u][b]
__device__ float g_emit[SEQ][NB][NTAG];         // emissions
__device__ int   g_cnt[2];                      // per-direction step barrier counters

extern __shared__ float sm[];

// ---------------- reset barrier counters ----------------
__global__ void k_reset() {
    if (threadIdx.x == 0) { g_cnt[0] = 0; g_cnt[1] = 0; }
}

// ---------------- embedding gather + transpose ----------------
__global__ void k_gather(const int* __restrict__ sent, const float* __restrict__ emb) {
    int s = blockIdx.x;
    __shared__ float sx[64][33];
    __shared__ int rows[64];
    int t = threadIdx.x;  // 256
    if (t < 64) rows[t] = sent[t * SEQ + s];
    __syncthreads();
    for (int kc = 0; kc < 10; kc++) {
        int kbase = kc * 32;
        int width = HID - kbase; if (width > 32) width = 32;
        int kk = t & 31, bg = t >> 5;
        if (kk < width) {
            for (int b = bg; b < 64; b += 8)
                sx[b][kk] = emb[rows[b] * HID + kbase + kk];
        }
        __syncthreads();
        int b = t & 63, kg = t >> 6;
        for (int k2 = kg; k2 < width; k2 += 4)
            g_XT[(s * HID + kbase + k2) * NB + b] = sx[b][k2];
        __syncthreads();
    }
}

// ---------------- input projection GEMM: G[d][s][row][b] = W_ih @ x + bias ----------------
__global__ void __launch_bounds__(R_THREADS, 1) k_inproj(
    const float* __restrict__ Wf, const float* __restrict__ bf,
    const float* __restrict__ Wb, const float* __restrict__ bb)
{
    int m = blockIdx.x, s = blockIdx.y, d = blockIdx.z;
    const float* W    = d ? Wb : Wf;
    const float* bias = d ? bb : bf;
    float* xs  = sm;               // 19200 floats
    float* ws  = sm + HID * NB;    // 18000 floats
    float* red = xs;               // aliased (xs dead after k-loop)
    int t = threadIdx.x;
    int u0 = m * IP_UPC;

    // stage weights: ws[k*60 + r], r = ul*4 + gate, row = gate*300 + u0 + ul
    for (int idx = t; idx < HID * IP_ROWS; idx += R_THREADS) {
        int k = idx / IP_ROWS, r = idx - k * IP_ROWS;
        int ul = r >> 2, gate = r & 3;
        ws[idx] = W[(gate * HID + u0 + ul) * HID + k];
    }
    // stage x
    {
        const float4* src = (const float4*)(g_XT + s * HID * NB);
        float4* dst = (float4*)xs;
        for (int idx = t; idx < HID * NB / 4; idx += R_THREADS) dst[idx] = src[idx];
    }
    __syncthreads();

    int b = t & 63, ks = t >> 6;
    float acc[IP_ROWS];
#pragma unroll
    for (int r = 0; r < IP_ROWS; r++) acc[r] = 0.f;
    int k0 = ks * R_KCH;
    for (int k = k0; k < k0 + R_KCH; k++) {
        float xv = xs[k * NB + b];
        const float4* w4 = (const float4*)(ws + k * IP_ROWS);
#pragma unroll
        for (int q = 0; q < IP_ROWS / 4; q++) {
            float4 w = w4[q];
            acc[4 * q + 0] += w.x * xv; acc[4 * q + 1] += w.y * xv;
            acc[4 * q + 2] += w.z * xv; acc[4 * q + 3] += w.w * xv;
        }
    }
    __syncthreads();  // xs reads complete before red (alias) writes
#pragma unroll
    for (int r = 0; r < IP_ROWS; r++) red[(ks * IP_ROWS + r) * NB + b] = acc[r];
    __syncthreads();

    float* Gd = g_G[d][s];
    for (int idx = t; idx < IP_ROWS * NB; idx += R_THREADS) {
        int r = idx >> 6, b2 = idx & 63;
        float v = 0.f;
#pragma unroll
        for (int kk = 0; kk < R_KS; kk++) v += red[(kk * IP_ROWS + r) * NB + b2];
        int ul = r >> 2, gate = r & 3;
        int row = gate * HID + u0 + ul;
        Gd[row * NB + b2] = v + bias[row];
    }
}

// ---------------- persistent LSTM recurrence (both directions) ----------------
__global__ void __launch_bounds__(R_THREADS, 1) k_recur(
    const float* __restrict__ Whf, const float* __restrict__ Whb)
{
    int d = (int)blockIdx.x / R_CTAS;
    int m = (int)blockIdx.x % R_CTAS;
    const float* W = d ? Whb : Whf;
    float* hs  = sm;                       // 19200 floats
    float* ws  = sm + HID * NB;            // 6000 floats
    float* red = ws + HID * R_ROWS;        // 6400 floats
    int t = threadIdx.x;
    int u0 = m * R_UPC;

    for (int idx = t; idx < HID * R_ROWS; idx += R_THREADS) {
        int k = idx / R_ROWS, r = idx - k * R_ROWS;
        int ul = r >> 2, gate = r & 3;
        ws[idx] = W[(gate * HID + u0 + ul) * HID + k];
    }
    __syncthreads();

    int b = t & 63, ks = t >> 6;   // ks doubles as u_local in the gate phase
    float c = 0.f;
    int target = 0;

    for (int step = 0; step < SEQ; step++) {
        int pos = d ? (SEQ - 1 - step) : step;
        const float* Gp = g_G[d][pos];
        int gbase = (u0 + ks) * NB + b;
        float a0, a1, a2, a3;

        if (step > 0) {
            int prev = d ? (SEQ - step) : (step - 1);
            const float4* src = (const float4*)(g_hall[d][prev]);
            float4* dst = (float4*)hs;
            for (int idx = t; idx < HID * NB / 4; idx += R_THREADS) dst[idx] = src[idx];
            __syncthreads();

            float acc[R_ROWS];
#pragma unroll
            for (int r = 0; r < R_ROWS; r++) acc[r] = 0.f;
            int k0 = ks * R_KCH;
#pragma unroll 2
            for (int k = k0; k < k0 + R_KCH; k++) {
                float hv = hs[k * NB + b];
                const float4* w4 = (const float4*)(ws + k * R_ROWS);
#pragma unroll
                for (int q = 0; q < R_ROWS / 4; q++) {
                    float4 w = w4[q];
                    acc[4 * q + 0] += w.x * hv; acc[4 * q + 1] += w.y * hv;
                    acc[4 * q + 2] += w.z * hv; acc[4 * q + 3] += w.w * hv;
                }
            }
#pragma unroll
            for (int r = 0; r < R_ROWS; r++) red[(ks * R_ROWS + r) * NB + b] = acc[r];
            __syncthreads();

            float v[4];
#pragma unroll
            for (int gate = 0; gate < 4; gate++) {
                int r = ks * 4 + gate;
                float x = 0.f;
#pragma unroll
                for (int kk = 0; kk < R_KS; kk++) x += red[(kk * R_ROWS + r) * NB + b];
                v[gate] = x + Gp[gate * HID * NB + gbase];
            }
            a0 = v[0]; a1 = v[1]; a2 = v[2]; a3 = v[3];
        } else {
            a0 = Gp[0 * HID * NB + gbase];
            a1 = Gp[1 * HID * NB + gbase];
            a2 = Gp[2 * HID * NB + gbase];
            a3 = Gp[3 * HID * NB + gbase];
        }

        float ig = 1.f / (1.f + expf(-a0));
        float fg = 1.f / (1.f + expf(-a1));
        float gg = tanhf(a2);
        float og = 1.f / (1.f + expf(-a3));
        c = fg * c + ig * gg;
        float h = og * tanhf(c);
        g_hall[d][pos][gbase] = h;

        // inter-CTA step barrier (per direction, monotonic counter)
        __threadfence();
        __syncthreads();
        target += R_CTAS;
        if (t == 0) {
            atomicAdd(&g_cnt[d], 1);
            while (atomicAdd(&g_cnt[d], 0) < target) { __nanosleep(40); }
        }
        __syncthreads();
    }
}

// ---------------- emissions: emit[s][b][j] = W_lin @ [h_f; h_b] + b_lin ----------------
__global__ void k_emit(const float* __restrict__ Wl, const float* __restrict__ bl) {
    int s = blockIdx.x, t = threadIdx.x;  // 256
    __shared__ float wl[600 * NTAG];
    __shared__ float red2[4 * NTAG * NB];
    for (int idx = t; idx < 600 * NTAG; idx += 256) {
        int k = idx / NTAG, j = idx - k * NTAG;
        wl[idx] = Wl[j * 600 + k];
    }
    __syncthreads();
    int b = t & 63, ks = t >> 6;
    float acc[NTAG];
#pragma unroll
    for (int j = 0; j < NTAG; j++) acc[j] = 0.f;
    const float* hf = g_hall[0][s];
    const float* hb = g_hall[1][s];
    int k0 = ks * 150;
    for (int k = k0; k < k0 + 150; k++) {
        float v = (k < HID) ? hf[k * NB + b] : hb[(k - HID) * NB + b];
        const float4* w4 = (const float4*)(wl + k * NTAG);
#pragma unroll
        for (int q = 0; q < 3; q++) {
            float4 w = w4[q];
            acc[4 * q + 0] += w.x * v; acc[4 * q + 1] += w.y * v;
            acc[4 * q + 2] += w.z * v; acc[4 * q + 3] += w.w * v;
        }
    }
#pragma unroll
    for (int j = 0; j < NTAG; j++) red2[(ks * NTAG + j) * NB + b] = acc[j];
    __syncthreads();
    for (int idx = t; idx < NTAG * NB; idx += 256) {
        int j = idx >> 6, b2 = idx & 63;
        float v = red2[(0 * NTAG + j) * NB + b2] + red2[(1 * NTAG + j) * NB + b2]
                + red2[(2 * NTAG + j) * NB + b2] + red2[(3 * NTAG + j) * NB + b2];
        g_emit[s][b2][j] = v + bl[j];
    }
}

// ---------------- CRF forward + gold score + loss (one warp per batch) ----------------
__global__ void k_crf(const int* __restrict__ tags, const float* __restrict__ trans,
                      float* __restrict__ out) {
    int b = blockIdx.x;
    int j = threadIdx.x;  // 32 lanes, lanes 0..11 carry tags
    float Tcol[NTAG];
#pragma unroll
    for (int i = 0; i < NTAG; i++) Tcol[i] = (j < NTAG) ? trans[i * NTAG + j] : 0.f;
    float dcur = (j < NTAG) ? g_emit[0][b][j] : -1e30f;

    // gold path score (all 32 lanes split the sequence)
    float ts = 0.f;
    for (int s = j; s < SEQ; s += 32) {
        int tg = tags[b * SEQ + s];
        ts += g_emit[s][b][tg];
        if (s < SEQ - 1) ts += trans[tg * NTAG + tags[b * SEQ + s + 1]];
    }
#pragma unroll
    for (int off = 16; off; off >>= 1) ts += __shfl_xor_sync(0xffffffffu, ts, off);

    // forward algorithm
    for (int s = 1; s < SEQ; s++) {
        float v[NTAG];
#pragma unroll
        for (int i = 0; i < NTAG; i++)
            v[i] = __shfl_sync(0xffffffffu, dcur, i) + Tcol[i];
        float mx = v[0];
#pragma unroll
        for (int i = 1; i < NTAG; i++) mx = fmaxf(mx, v[i]);
        float sum = 0.f;
#pragma unroll
        for (int i = 0; i < NTAG; i++) sum += expf(v[i] - mx);
        float e = (j < NTAG) ? g_emit[s][b][j] : 0.f;
        dcur = e + mx + logf(sum);
    }

    float dd = (j < NTAG) ? dcur : -1e30f;
    float mm = dd;
#pragma unroll
    for (int off = 16; off; off >>= 1) mm = fmaxf(mm, __shfl_xor_sync(0xffffffffu, mm, off));
    float se = (j < NTAG) ? expf(dd - mm) : 0.f;
#pragma unroll
    for (int off = 16; off; off >>= 1) se += __shfl_xor_sync(0xffffffffu, se, off);
    if (j == 0) out[b] = mm + logf(se) - ts;
}

// ---------------- launch ----------------
extern "C" void kernel_launch(void* const* d_in, const int* in_sizes, int n_in,
                              void* d_out, int out_size) {
    const int*   sentences = (const int*)d_in[0];
    const int*   tags      = (const int*)d_in[1];
    const float* emb       = (const float*)d_in[2];
    const float* W_ih_f    = (const float*)d_in[3];
    const float* W_hh_f    = (const float*)d_in[4];
    const float* b_f       = (const float*)d_in[5];
    const float* W_ih_b    = (const float*)d_in[6];
    const float* W_hh_b    = (const float*)d_in[7];
    const float* b_b       = (const float*)d_in[8];
    const float* W_lin     = (const float*)d_in[9];
    const float* b_lin     = (const float*)d_in[10];
    const float* trans     = (const float*)d_in[11];
    float* out = (float*)d_out;

    int smem_ip = (HID * NB + HID * IP_ROWS) * 4;                       // 148800 B
    int smem_rc = (HID * NB + HID * R_ROWS + R_KS * R_ROWS * NB) * 4;   // 126400 B
    cudaFuncSetAttribute(k_inproj, cudaFuncAttributeMaxDynamicSharedMemorySize, smem_ip);
    cudaFuncSetAttribute(k_recur,  cudaFuncAttributeMaxDynamicSharedMemorySize, smem_rc);

    k_reset<<<1, 32>>>();
    k_gather<<<SEQ, 256>>>(sentences, emb);
    dim3 gip(IP_MB, SEQ, 2);
    k_inproj<<<gip, R_THREADS, smem_ip>>>(W_ih_f, b_f, W_ih_b, b_b);
    k_recur<<<2 * R_CTAS, R_THREADS, smem_rc>>>(W_hh_f, W_hh_b);
    k_emit<<<SEQ, 256>>>(W_lin, b_lin);
    k_crf<<<NB, 32>>>(tags, trans, out);
}

// round 2
// speedup vs baseline: 1.0570x; 1.0570x over previous
#include <cuda_runtime.h>
#include <math.h>

#define SEQ 256
#define NB 64
#define HID 300
#define G4 1200
#define NTAG 12

// recurrence config: 60 CTAs per direction, each owns 5 hidden units (20 gate rows)
#define R_CTAS 60
#define R_UPC 5
#define R_THREADS 640

// input-projection config: 20 CTAs of 60 gate rows cover the 1200 rows
#define IP_MB 20
#define IP_ROWS 60
#define IP_THREADS 320

typedef unsigned long long ull;

__device__ __forceinline__ ull pack2(float lo, float hi) {
    ull r; asm("mov.b64 %0, {%1, %2};" : "=l"(r) : "f"(lo), "f"(hi)); return r;
}
__device__ __forceinline__ void unpack2(ull v, float& lo, float& hi) {
    asm("mov.b64 {%0, %1}, %2;" : "=f"(lo), "=f"(hi) : "l"(v));
}
__device__ __forceinline__ ull fma2(ull a, ull b, ull c) {
    ull d; asm("fma.rn.f32x2 %0, %1, %2, %3;" : "=l"(d) : "l"(a), "l"(b), "l"(c)); return d;
}
__device__ __forceinline__ ull add2(ull a, ull b) {
    ull d; asm("add.rn.f32x2 %0, %1, %2;" : "=l"(d) : "l"(a), "l"(b)); return d;
}
__device__ __forceinline__ float ftanh(float x) {
    float y; asm("tanh.approx.f32 %0, %1;" : "=f"(y) : "f"(x)); return y;
}
__device__ __forceinline__ float fsigm(float x) {
    return 0.5f * ftanh(0.5f * x) + 0.5f;
}

// ---------------- scratch (device globals; no allocations) ----------------
__device__ float g_XT[SEQ * HID * NB];          // x transposed per step: [s][k][b]
__device__ float g_G[2][SEQ][G4 * NB];          // input projections + bias: [d][s][row][b]
__device__ float g_hall[2][SEQ][HID * NB];      // hidden states: [d][s][u][b]
__device__ float g_emit[SEQ][NB][NTAG];         // emissions
__device__ int   g_cnt[2];                      // per-direction step barrier counters

extern __shared__ float sm[];

// ---------------- reset barrier counters ----------------
__global__ void k_reset() {
    if (threadIdx.x == 0) { g_cnt[0] = 0; g_cnt[1] = 0; }
}

// ---------------- embedding gather + transpose ----------------
__global__ void k_gather(const int* __restrict__ sent, const float* __restrict__ emb) {
    int s = blockIdx.x;
    __shared__ float sx[64][33];
    __shared__ int rows[64];
    int t = threadIdx.x;  // 256
    if (t < 64) rows[t] = sent[t * SEQ + s];
    __syncthreads();
    for (int kc = 0; kc < 10; kc++) {
        int kbase = kc * 32;
        int width = HID - kbase; if (width > 32) width = 32;
        int kk = t & 31, bg = t >> 5;
        if (kk < width) {
            for (int b = bg; b < 64; b += 8)
                sx[b][kk] = emb[rows[b] * HID + kbase + kk];
        }
        __syncthreads();
        int b = t & 63, kg = t >> 6;
        for (int k2 = kg; k2 < width; k2 += 4)
            g_XT[(s * HID + kbase + k2) * NB + b] = sx[b][k2];
        __syncthreads();
    }
}

// ---------------- input projection GEMM: G[d][s][row][b] = W_ih @ x + bias ----------------
// 320 threads = 64 batch x 5 row-groups; each thread: 12 rows x K=300, f32x2 FMAs
__global__ void __launch_bounds__(IP_THREADS, 1) k_inproj(
    const float* __restrict__ Wf, const float* __restrict__ bf,
    const float* __restrict__ Wb, const float* __restrict__ bb)
{
    int m = blockIdx.x, s = blockIdx.y, d = blockIdx.z;
    const float* W    = d ? Wb : Wf;
    const float* bias = d ? bb : bf;
    float* xs  = sm;               // 19200 floats
    float* ws  = sm + HID * NB;    // 18000 floats: ws[k*60 + r]
    int t = threadIdx.x;
    int u0 = m * 15;

    // stage weights: ws[k*60 + r], r = ul*4 + gate, row = gate*300 + u0 + ul
    for (int idx = t; idx < HID * IP_ROWS; idx += IP_THREADS) {
        int k = idx / IP_ROWS, r = idx - k * IP_ROWS;
        int ul = r >> 2, gate = r & 3;
        ws[idx] = W[(gate * HID + u0 + ul) * HID + k];
    }
    // stage x
    {
        const float4* src = (const float4*)(g_XT + s * HID * NB);
        float4* dst = (float4*)xs;
        for (int idx = t; idx < HID * NB / 4; idx += IP_THREADS) dst[idx] = src[idx];
    }
    __syncthreads();

    int b = t & 63, rg = t >> 6;   // rg 0..4, owns rows rg*12 .. rg*12+11
    ull acc[6];
#pragma unroll
    for (int p = 0; p < 6; p++) acc[p] = 0ull;

    const ulonglong2* wp = ((const ulonglong2*)ws) + rg * 3;  // 3 x 16B = 12 floats
    const float* xp = xs + b;
#pragma unroll 4
    for (int k = 0; k < HID; k++) {
        float hv = xp[k * NB];
        ull h2 = pack2(hv, hv);
        ulonglong2 w0 = wp[0], w1 = wp[1], w2 = wp[2];
        acc[0] = fma2(w0.x, h2, acc[0]);
        acc[1] = fma2(w0.y, h2, acc[1]);
        acc[2] = fma2(w1.x, h2, acc[2]);
        acc[3] = fma2(w1.y, h2, acc[3]);
        acc[4] = fma2(w2.x, h2, acc[4]);
        acc[5] = fma2(w2.y, h2, acc[5]);
        wp += 15;  // 60 floats per k
    }

    float* Gd = g_G[d][s];
#pragma unroll
    for (int p = 0; p < 6; p++) {
        float v0, v1; unpack2(acc[p], v0, v1);
        int r0 = rg * 12 + 2 * p, r1 = r0 + 1;
        int row0 = (r0 & 3) * HID + u0 + (r0 >> 2);
        int row1 = (r1 & 3) * HID + u0 + (r1 >> 2);
        Gd[row0 * NB + b] = v0 + bias[row0];
        Gd[row1 * NB + b] = v1 + bias[row1];
    }
}

// ---------------- persistent LSTM recurrence (both directions) ----------------
// 640 threads = 64 batch x 5 units x 2 K-halves
__global__ void __launch_bounds__(R_THREADS, 1) k_recur(
    const float* __restrict__ Whf, const float* __restrict__ Whb)
{
    int d = (int)blockIdx.x / R_CTAS;
    int m = (int)blockIdx.x % R_CTAS;
    const float* W = d ? Whb : Whf;
    float* hs  = sm;                       // 19200 floats
    float* ws  = sm + HID * NB;            // 6000 floats: ws[(k*5+ul)*4+gate]
    float* red = ws + HID * 4 * R_UPC;     // 1280 floats: red[ul][b][4]
    int t = threadIdx.x;
    int u0 = m * R_UPC;

    for (int idx = t; idx < HID * 4 * R_UPC; idx += R_THREADS) {
        int k = idx / 20, rem = idx - k * 20;
        int ul = rem >> 2, gate = rem & 3;
        ws[idx] = W[(gate * HID + u0 + ul) * HID + k];
    }
    __syncthreads();

    int b = t & 63, slot = t >> 6;       // slot 0..9
    int ul = slot % R_UPC, kh = slot / R_UPC;
    int gbase = (u0 + ul) * NB + b;
    float c = 0.f;
    int target = 0;

    for (int step = 0; step < SEQ; step++) {
        int pos = d ? (SEQ - 1 - step) : step;
        const float* Gp = g_G[d][pos];
        float a0, a1, a2, a3;
        bool havea = false;

        if (step > 0) {
            int prev = d ? (SEQ - step) : (step - 1);
            const float4* src = (const float4*)(g_hall[d][prev]);
            float4* dst = (float4*)hs;
            for (int idx = t; idx < HID * NB / 4; idx += R_THREADS) dst[idx] = src[idx];
            __syncthreads();

            ull acc0 = 0ull, acc1 = 0ull;
            int k0 = kh * 150;
            const float* hp = hs + k0 * NB + b;
            const ulonglong2* wp = ((const ulonglong2*)ws) + (k0 * R_UPC + ul);
#pragma unroll 5
            for (int kk = 0; kk < 150; kk++) {
                float hv = hp[kk * NB];
                ull h2 = pack2(hv, hv);
                ulonglong2 w = wp[kk * R_UPC];
                acc0 = fma2(w.x, h2, acc0);
                acc1 = fma2(w.y, h2, acc1);
            }
            if (kh == 1) {
                ulonglong2 v; v.x = acc0; v.y = acc1;
                ((ulonglong2*)red)[ul * NB + b] = v;
            }
            __syncthreads();
            if (kh == 0) {
                ulonglong2 r2 = ((ulonglong2*)red)[ul * NB + b];
                acc0 = add2(acc0, r2.x);
                acc1 = add2(acc1, r2.y);
                unpack2(acc0, a0, a1);
                unpack2(acc1, a2, a3);
                a0 += Gp[0 * HID * NB + gbase];
                a1 += Gp[1 * HID * NB + gbase];
                a2 += Gp[2 * HID * NB + gbase];
                a3 += Gp[3 * HID * NB + gbase];
                havea = true;
            }
        } else if (kh == 0) {
            a0 = Gp[0 * HID * NB + gbase];
            a1 = Gp[1 * HID * NB + gbase];
            a2 = Gp[2 * HID * NB + gbase];
            a3 = Gp[3 * HID * NB + gbase];
            havea = true;
        }

        if (havea) {
            float ig = fsigm(a0);
            float fg = fsigm(a1);
            float gg = ftanh(a2);
            float og = fsigm(a3);
            c = fg * c + ig * gg;
            float h = og * ftanh(c);
            g_hall[d][pos][gbase] = h;
        }

        // inter-CTA step barrier (per direction, monotonic counter)
        __threadfence();
        __syncthreads();
        target += R_CTAS;
        if (t == 0) {
            atomicAdd(&g_cnt[d], 1);
            const int* cp = &g_cnt[d];
            int v;
            do {
                asm volatile("ld.acquire.gpu.global.b32 %0, [%1];" : "=r"(v) : "l"(cp) : "memory");
                if (v < target) __nanosleep(20);
            } while (v < target);
        }
        __syncthreads();
    }
}

// ---------------- emissions: emit[s][b][j] = W_lin @ [h_f; h_b] + b_lin ----------------
__global__ void k_emit(const float* __restrict__ Wl, const float* __restrict__ bl) {
    int s = blockIdx.x, t = threadIdx.x;  // 256
    __shared__ float wl[600 * NTAG];
    __shared__ float red2[4 * NTAG * NB];
    for (int idx = t; idx < 600 * NTAG; idx += 256) {
        int k = idx / NTAG, j = idx - k * NTAG;
        wl[idx] = Wl[j * 600 + k];
    }
    __syncthreads();
    int b = t & 63, ks = t >> 6;
    float acc[NTAG];
#pragma unroll
    for (int j = 0; j < NTAG; j++) acc[j] = 0.f;
    const float* hf = g_hall[0][s];
    const float* hb = g_hall[1][s];
    int k0 = ks * 150;
    for (int k = k0; k < k0 + 150; k++) {
        float v = (k < HID) ? hf[k * NB + b] : hb[(k - HID) * NB + b];
        const float4* w4 = (const float4*)(wl + k * NTAG);
#pragma unroll
        for (int q = 0; q < 3; q++) {
            float4 w = w4[q];
            acc[4 * q + 0] += w.x * v; acc[4 * q + 1] += w.y * v;
            acc[4 * q + 2] += w.z * v; acc[4 * q + 3] += w.w * v;
        }
    }
#pragma unroll
    for (int j = 0; j < NTAG; j++) red2[(ks * NTAG + j) * NB + b] = acc[j];
    __syncthreads();
    for (int idx = t; idx < NTAG * NB; idx += 256) {
        int j = idx >> 6, b2 = idx & 63;
        float v = red2[(0 * NTAG + j) * NB + b2] + red2[(1 * NTAG + j) * NB + b2]
                + red2[(2 * NTAG + j) * NB + b2] + red2[(3 * NTAG + j) * NB + b2];
        g_emit[s][b2][j] = v + bl[j];
    }
}

// ---------------- CRF forward + gold score + loss (one warp per batch) ----------------
__global__ void k_crf(const int* __restrict__ tags, const float* __restrict__ trans,
                      float* __restrict__ out) {
    int b = blockIdx.x;
    int j = threadIdx.x;  // 32 lanes, lanes 0..11 carry tags
    float Tcol[NTAG];
#pragma unroll
    for (int i = 0; i < NTAG; i++) Tcol[i] = (j < NTAG) ? trans[i * NTAG + j] : 0.f;
    float dcur = (j < NTAG) ? g_emit[0][b][j] : -1e30f;

    // gold path score (all 32 lanes split the sequence)
    float ts = 0.f;
    for (int s = j; s < SEQ; s += 32) {
        int tg = tags[b * SEQ + s];
        ts += g_emit[s][b][tg];
        if (s < SEQ - 1) ts += trans[tg * NTAG + tags[b * SEQ + s + 1]];
    }
#pragma unroll
    for (int off = 16; off; off >>= 1) ts += __shfl_xor_sync(0xffffffffu, ts, off);

    // forward algorithm
    for (int s = 1; s < SEQ; s++) {
        float v[NTAG];
#pragma unroll
        for (int i = 0; i < NTAG; i++)
            v[i] = __shfl_sync(0xffffffffu, dcur, i) + Tcol[i];
        float mx = v[0];
#pragma unroll
        for (int i = 1; i < NTAG; i++) mx = fmaxf(mx, v[i]);
        float sum = 0.f;
#pragma unroll
        for (int i = 0; i < NTAG; i++) sum += expf(v[i] - mx);
        float e = (j < NTAG) ? g_emit[s][b][j] : 0.f;
        dcur = e + mx + logf(sum);
    }

    float dd = (j < NTAG) ? dcur : -1e30f;
    float mm = dd;
#pragma unroll
    for (int off = 16; off; off >>= 1) mm = fmaxf(mm, __shfl_xor_sync(0xffffffffu, mm, off));
    float se = (j < NTAG) ? expf(dd - mm) : 0.f;
#pragma unroll
    for (int off = 16; off; off >>= 1) se += __shfl_xor_sync(0xffffffffu, se, off);
    if (j == 0) out[b] = mm + logf(se) - ts;
}

// ---------------- launch ----------------
extern "C" void kernel_launch(void* const* d_in, const int* in_sizes, int n_in,
                              void* d_out, int out_size) {
    const int*   sentences = (const int*)d_in[0];
    const int*   tags      = (const int*)d_in[1];
    const float* emb       = (const float*)d_in[2];
    const float* W_ih_f    = (const float*)d_in[3];
    const float* W_hh_f    = (const float*)d_in[4];
    const float* b_f       = (const float*)d_in[5];
    const float* W_ih_b    = (const float*)d_in[6];
    const float* W_hh_b    = (const float*)d_in[7];
    const float* b_b       = (const float*)d_in[8];
    const float* W_lin     = (const float*)d_in[9];
    const float* b_lin     = (const float*)d_in[10];
    const float* trans     = (const float*)d_in[11];
    float* out = (float*)d_out;

    int smem_ip = (HID * NB + HID * IP_ROWS) * 4;                        // 148800 B
    int smem_rc = (HID * NB + HID * 4 * R_UPC + R_UPC * 4 * NB) * 4;     // 105920 B
    cudaFuncSetAttribute(k_inproj, cudaFuncAttributeMaxDynamicSharedMemorySize, smem_ip);
    cudaFuncSetAttribute(k_recur,  cudaFuncAttributeMaxDynamicSharedMemorySize, smem_rc);

    k_reset<<<1, 32>>>();
    k_gather<<<SEQ, 256>>>(sentences, emb);
    dim3 gip(IP_MB, SEQ, 2);
    k_inproj<<<gip, IP_THREADS, smem_ip>>>(W_ih_f, b_f, W_ih_b, b_b);
    k_recur<<<2 * R_CTAS, R_THREADS, smem_rc>>>(W_hh_f, W_hh_b);
    k_emit<<<SEQ, 256>>>(W_lin, b_lin);
    k_crf<<<NB, 32>>>(tags, trans, out);
}

// round 3
// speedup vs baseline: 1.1153x; 1.0551x over previous
#include <cuda_runtime.h>
#include <math.h>

#define SEQ 256
#define NB 64
#define HID 300
#define G4 1200
#define NTAG 12

// recurrence: 2 dirs x 8 batch-groups x 8 unit-slices = 128 CTAs (one wave)
#define RBG 8           // batch groups
#define RUS 8           // unit slices
#define RBS 8           // batch per group
#define RUPC 38         // units per slice (last slice has 34)
#define R_P 76          // row pairs (152 gate rows / 2)
#define R_KSPLIT 4
#define R_KCH 75
#define R_THREADS 320   // 304 active = 4 ksplit x 76 rowpairs

// input-projection config: 20 CTAs of 60 gate rows cover the 1200 rows
#define IP_MB 20
#define IP_ROWS 60
#define IP_THREADS 320

typedef unsigned long long ull;

__device__ __forceinline__ ull pack2(float lo, float hi) {
    ull r; asm("mov.b64 %0, {%1, %2};" : "=l"(r) : "f"(lo), "f"(hi)); return r;
}
__device__ __forceinline__ void unpack2(ull v, float& lo, float& hi) {
    asm("mov.b64 {%0, %1}, %2;" : "=f"(lo), "=f"(hi) : "l"(v));
}
__device__ __forceinline__ ull fma2(ull a, ull b, ull c) {
    ull d; asm("fma.rn.f32x2 %0, %1, %2, %3;" : "=l"(d) : "l"(a), "l"(b), "l"(c)); return d;
}
__device__ __forceinline__ ull add2(ull a, ull b) {
    ull d; asm("add.rn.f32x2 %0, %1, %2;" : "=l"(d) : "l"(a), "l"(b)); return d;
}
__device__ __forceinline__ float ftanh(float x) {
    float y; asm("tanh.approx.f32 %0, %1;" : "=f"(y) : "f"(x)); return y;
}
__device__ __forceinline__ float fsigm(float x) {
    return 0.5f * ftanh(0.5f * x) + 0.5f;
}

// ---------------- scratch (device globals; no allocations) ----------------
__device__ float g_XT[SEQ * HID * NB];             // x transposed: [s][k][b]
__device__ float g_G[2][SEQ][G4 * NB];             // input proj + bias: [d][s][row][b]
__device__ float g_hall[2][SEQ][RBG * HID * RBS];  // h: [d][s][group][u*8+bo]
__device__ float g_emit[SEQ][NB][NTAG];            // emissions
__device__ int   g_cnt2[16];                       // per (dir,group) barrier counters

extern __shared__ float sm[];

// ---------------- reset barrier counters ----------------
__global__ void k_reset() {
    if (threadIdx.x < 16) g_cnt2[threadIdx.x] = 0;
}

// ---------------- embedding gather + transpose ----------------
__global__ void k_gather(const int* __restrict__ sent, const float* __restrict__ emb) {
    int s = blockIdx.x;
    __shared__ float sx[64][33];
    __shared__ int rows[64];
    int t = threadIdx.x;  // 256
    if (t < 64) rows[t] = sent[t * SEQ + s];
    __syncthreads();
    for (int kc = 0; kc < 10; kc++) {
        int kbase = kc * 32;
        int width = HID - kbase; if (width > 32) width = 32;
        int kk = t & 31, bg = t >> 5;
        if (kk < width) {
            for (int b = bg; b < 64; b += 8)
                sx[b][kk] = emb[rows[b] * HID + kbase + kk];
        }
        __syncthreads();
        int b = t & 63, kg = t >> 6;
        for (int k2 = kg; k2 < width; k2 += 4)
            g_XT[(s * HID + kbase + k2) * NB + b] = sx[b][k2];
        __syncthreads();
    }
}

// ---------------- input projection GEMM: G[d][s][row][b] = W_ih @ x + bias ----------------
__global__ void __launch_bounds__(IP_THREADS, 1) k_inproj(
    const float* __restrict__ Wf, const float* __restrict__ bf,
    const float* __restrict__ Wb, const float* __restrict__ bb)
{
    int m = blockIdx.x, s = blockIdx.y, d = blockIdx.z;
    const float* W    = d ? Wb : Wf;
    const float* bias = d ? bb : bf;
    float* xs  = sm;               // 19200 floats
    float* ws  = sm + HID * NB;    // 18000 floats: ws[k*60 + r]
    int t = threadIdx.x;
    int u0 = m * 15;

    for (int idx = t; idx < HID * IP_ROWS; idx += IP_THREADS) {
        int k = idx / IP_ROWS, r = idx - k * IP_ROWS;
        int ul = r >> 2, gate = r & 3;
        ws[idx] = W[(gate * HID + u0 + ul) * HID + k];
    }
    {
        const float4* src = (const float4*)(g_XT + s * HID * NB);
        float4* dst = (float4*)xs;
        for (int idx = t; idx < HID * NB / 4; idx += IP_THREADS) dst[idx] = src[idx];
    }
    __syncthreads();

    int b = t & 63, rg = t >> 6;   // rg 0..4, owns rows rg*12 .. rg*12+11
    ull acc[6];
#pragma unroll
    for (int p = 0; p < 6; p++) acc[p] = 0ull;

    const ulonglong2* wp = ((const ulonglong2*)ws) + rg * 3;
    const float* xp = xs + b;
#pragma unroll 4
    for (int k = 0; k < HID; k++) {
        float hv = xp[k * NB];
        ull h2 = pack2(hv, hv);
        ulonglong2 w0 = wp[0], w1 = wp[1], w2 = wp[2];
        acc[0] = fma2(w0.x, h2, acc[0]);
        acc[1] = fma2(w0.y, h2, acc[1]);
        acc[2] = fma2(w1.x, h2, acc[2]);
        acc[3] = fma2(w1.y, h2, acc[3]);
        acc[4] = fma2(w2.x, h2, acc[4]);
        acc[5] = fma2(w2.y, h2, acc[5]);
        wp += 15;
    }

    float* Gd = g_G[d][s];
#pragma unroll
    for (int p = 0; p < 6; p++) {
        float v0, v1; unpack2(acc[p], v0, v1);
        int r0 = rg * 12 + 2 * p, r1 = r0 + 1;
        int row0 = (r0 & 3) * HID + u0 + (r0 >> 2);
        int row1 = (r1 & 3) * HID + u0 + (r1 >> 2);
        Gd[row0 * NB + b] = v0 + bias[row0];
        Gd[row1 * NB + b] = v1 + bias[row1];
    }
}

// ---------------- persistent LSTM recurrence, 2D (batch-group x unit-slice) ----------------
// CTA = (d, g, m). Owns units [m*38, m*38+cu) and batches [g*8, g*8+8).
// smem: ws 45600 f | hs 2400 f | red 4864 f (2432 ull)
__global__ void __launch_bounds__(R_THREADS, 1) k_recur(
    const float* __restrict__ Whf, const float* __restrict__ Whb)
{
    int bid = blockIdx.x;
    int d = bid >> 6;
    int g = (bid >> 3) & 7;
    int m = bid & 7;
    const float* W = d ? Whb : Whf;

    float* ws = sm;                    // ws[k*152 + r], r = ul*4+gate (pairs packed)
    float* hs = sm + HID * 152;        // hs[k*8 + bo]
    ull*  red = (ull*)(hs + HID * RBS);

    int t = threadIdx.x;
    int u0 = m * RUPC;
    int cu = HID - u0; if (cu > RUPC) cu = RUPC;

    // stage weights (zero-padded beyond cu)
    for (int idx = t; idx < HID * 152; idx += R_THREADS) {
        int k = idx / 152, r = idx - k * 152;
        int ul = r >> 2, gate = r & 3;
        ws[idx] = (ul < cu) ? W[(gate * HID + u0 + ul) * HID + k] : 0.f;
    }
    __syncthreads();

    int ks = t / R_P;          // 0..3 active, 4 = spare
    int p  = t - ks * R_P;     // rowpair 0..75
    int k0 = (ks & 3) * R_KCH;
    int bp = (ks > 3) ? 3 : ks;        // phase2 batch-pair (clamped for spares)
    int ul = p >> 1;
    bool doer = (t < 304) && ((p & 1) == 0) && (ul < cu);
    int boff = g * RBS + bp * 2;
    float c0 = 0.f, c1 = 0.f;
    int* cnt = &g_cnt2[d * 8 + g];
    const ull* wsu = (const ull*)ws;
    const ulonglong2* hsu = (const ulonglong2*)hs;

    for (int step = 0; step < SEQ; step++) {
        int pos = d ? (SEQ - 1 - step) : step;
        const float* Gp = g_G[d][pos];

        // prefetch this step's G (hidden under the barrier wait)
        float2 Gv0, Gv1, Gv2, Gv3;
        if (doer) {
            int gb = (u0 + ul) * NB + boff;
            Gv0 = *(const float2*)(Gp + 0 * HID * NB + gb);
            Gv1 = *(const float2*)(Gp + 1 * HID * NB + gb);
            Gv2 = *(const float2*)(Gp + 2 * HID * NB + gb);
            Gv3 = *(const float2*)(Gp + 3 * HID * NB + gb);
        }

        float s0lo = 0.f, s0hi = 0.f, s1lo = 0.f, s1hi = 0.f;

        if (step > 0) {
            // wait for group h of previous step
            if (t == 0) {
                int target = RUS * step;
                int v;
                do {
                    asm volatile("ld.acquire.gpu.global.b32 %0, [%1];" : "=r"(v) : "l"(cnt) : "memory");
                    if (v < target) __nanosleep(20);
                } while (v < target);
            }
            __syncthreads();

            // stage group h slab (9.6KB)
            {
                int prev = d ? (SEQ - step) : (step - 1);
                const float4* src = (const float4*)(g_hall[d][prev] + g * (HID * RBS));
                float4* dst = (float4*)hs;
                for (int idx = t; idx < HID * RBS / 4; idx += R_THREADS) dst[idx] = src[idx];
            }
            __syncthreads();

            // partial GEMV: 2 rows x 8 batches per thread over 75 k's
            ull a00 = 0, a01 = 0, a02 = 0, a03 = 0;
            ull a10 = 0, a11 = 0, a12 = 0, a13 = 0;
#pragma unroll 5
            for (int kk = 0; kk < R_KCH; kk++) {
                int k = k0 + kk;
                ull w = wsu[k * R_P + p];
                float w0, w1; unpack2(w, w0, w1);
                ull w00 = pack2(w0, w0), w11 = pack2(w1, w1);
                ulonglong2 hA = hsu[k * 2];
                ulonglong2 hB = hsu[k * 2 + 1];
                a00 = fma2(w00, hA.x, a00); a01 = fma2(w00, hA.y, a01);
                a02 = fma2(w00, hB.x, a02); a03 = fma2(w00, hB.y, a03);
                a10 = fma2(w11, hA.x, a10); a11 = fma2(w11, hA.y, a11);
                a12 = fma2(w11, hB.x, a12); a13 = fma2(w11, hB.y, a13);
            }
            if (t < 304) {
                // red[((p*8 + bpw*2 + row))*4 + ks]
                int base = p * 32 + ks;
                red[base + 0 * 8 + 0] = a00; red[base + 1 * 8 + 0] = a01;
                red[base + 2 * 8 + 0] = a02; red[base + 3 * 8 + 0] = a03;
                red[base + 0 * 8 + 4] = a10; red[base + 1 * 8 + 4] = a11;
                red[base + 2 * 8 + 4] = a12; red[base + 3 * 8 + 4] = a13;
            }
            __syncthreads();

            // phase2: thread (p, bp) sums 4 k-splits for rows 2p,2p+1 (2 batches)
            {
                const ulonglong2* r2 = (const ulonglong2*)red;
                int ib = (p * 8 + bp * 2) * 2;
                ulonglong2 q0 = r2[ib + 0], q1 = r2[ib + 1];        // row0 ks0..3
                ulonglong2 q2 = r2[ib + 2], q3 = r2[ib + 3];        // row1 ks0..3
                ull s0 = add2(add2(q0.x, q0.y), add2(q1.x, q1.y));
                ull s1 = add2(add2(q2.x, q2.y), add2(q3.x, q3.y));
                unpack2(s0, s0lo, s0hi);
                unpack2(s1, s1lo, s1hi);
            }
        }

        // exchange: even-p thread (gates i,f) pulls gates g,o from odd partner (t+1)
        float g2lo = __shfl_down_sync(0xffffffffu, s0lo, 1);
        float g2hi = __shfl_down_sync(0xffffffffu, s0hi, 1);
        float g3lo = __shfl_down_sync(0xffffffffu, s1lo, 1);
        float g3hi = __shfl_down_sync(0xffffffffu, s1hi, 1);

        if (doer) {
            float i0 = fsigm(s0lo + Gv0.x), i1 = fsigm(s0hi + Gv0.y);
            float f0 = fsigm(s1lo + Gv1.x), f1 = fsigm(s1hi + Gv1.y);
            float q0 = ftanh(g2lo + Gv2.x), q1 = ftanh(g2hi + Gv2.y);
            float o0 = fsigm(g3lo + Gv3.x), o1 = fsigm(g3hi + Gv3.y);
            c0 = f0 * c0 + i0 * q0;
            c1 = f1 * c1 + i1 * q1;
            float2 hv;
            hv.x = o0 * ftanh(c0);
            hv.y = o1 * ftanh(c1);
            *(float2*)(g_hall[d][pos] + g * (HID * RBS) + (u0 + ul) * RBS + bp * 2) = hv;
        }

        __threadfence();
        __syncthreads();
        if (t == 0) atomicAdd(cnt, 1);
    }
}

// ---------------- emissions: emit[s][b][j] = W_lin @ [h_f; h_b] + b_lin ----------------
__global__ void k_emit(const float* __restrict__ Wl, const float* __restrict__ bl) {
    int s = blockIdx.x, t = threadIdx.x;  // 256
    __shared__ float wl[600 * NTAG];
    __shared__ float red2[4 * NTAG * NB];
    for (int idx = t; idx < 600 * NTAG; idx += 256) {
        int k = idx / NTAG, j = idx - k * NTAG;
        wl[idx] = Wl[j * 600 + k];
    }
    __syncthreads();
    int b = t & 63, ksx = t >> 6;
    int gof = (b >> 3) * (HID * RBS) + (b & 7);
    float acc[NTAG];
#pragma unroll
    for (int j = 0; j < NTAG; j++) acc[j] = 0.f;
    const float* hf = g_hall[0][s];
    const float* hb = g_hall[1][s];
    int k0 = ksx * 150;
    for (int k = k0; k < k0 + 150; k++) {
        float v = (k < HID) ? hf[gof + k * RBS] : hb[gof + (k - HID) * RBS];
        const float4* w4 = (const float4*)(wl + k * NTAG);
#pragma unroll
        for (int q = 0; q < 3; q++) {
            float4 w = w4[q];
            acc[4 * q + 0] += w.x * v; acc[4 * q + 1] += w.y * v;
            acc[4 * q + 2] += w.z * v; acc[4 * q + 3] += w.w * v;
        }
    }
#pragma unroll
    for (int j = 0; j < NTAG; j++) red2[(ksx * NTAG + j) * NB + b] = acc[j];
    __syncthreads();
    for (int idx = t; idx < NTAG * NB; idx += 256) {
        int j = idx >> 6, b2 = idx & 63;
        float v = red2[(0 * NTAG + j) * NB + b2] + red2[(1 * NTAG + j) * NB + b2]
                + red2[(2 * NTAG + j) * NB + b2] + red2[(3 * NTAG + j) * NB + b2];
        g_emit[s][b2][j] = v + bl[j];
    }
}

// ---------------- CRF forward + gold score + loss (one warp per batch) ----------------
__global__ void k_crf(const int* __restrict__ tags, const float* __restrict__ trans,
                      float* __restrict__ out) {
    int b = blockIdx.x;
    int j = threadIdx.x;
    float Tcol[NTAG];
#pragma unroll
    for (int i = 0; i < NTAG; i++) Tcol[i] = (j < NTAG) ? trans[i * NTAG + j] : 0.f;
    float dcur = (j < NTAG) ? g_emit[0][b][j] : -1e30f;

    float ts = 0.f;
    for (int s = j; s < SEQ; s += 32) {
        int tg = tags[b * SEQ + s];
        ts += g_emit[s][b][tg];
        if (s < SEQ - 1) ts += trans[tg * NTAG + tags[b * SEQ + s + 1]];
    }
#pragma unroll
    for (int off = 16; off; off >>= 1) ts += __shfl_xor_sync(0xffffffffu, ts, off);

    for (int s = 1; s < SEQ; s++) {
        float v[NTAG];
#pragma unroll
        for (int i = 0; i < NTAG; i++)
            v[i] = __shfl_sync(0xffffffffu, dcur, i) + Tcol[i];
        float mx = v[0];
#pragma unroll
        for (int i = 1; i < NTAG; i++) mx = fmaxf(mx, v[i]);
        float sum = 0.f;
#pragma unroll
        for (int i = 0; i < NTAG; i++) sum += expf(v[i] - mx);
        float e = (j < NTAG) ? g_emit[s][b][j] : 0.f;
        dcur = e + mx + logf(sum);
    }

    float dd = (j < NTAG) ? dcur : -1e30f;
    float mm = dd;
#pragma unroll
    for (int off = 16; off; off >>= 1) mm = fmaxf(mm, __shfl_xor_sync(0xffffffffu, mm, off));
    float se = (j < NTAG) ? expf(dd - mm) : 0.f;
#pragma unroll
    for (int off = 16; off; off >>= 1) se += __shfl_xor_sync(0xffffffffu, se, off);
    if (j == 0) out[b] = mm + logf(se) - ts;
}

// ---------------- launch ----------------
extern "C" void kernel_launch(void* const* d_in, const int* in_sizes, int n_in,
                              void* d_out, int out_size) {
    const int*   sentences = (const int*)d_in[0];
    const int*   tags      = (const int*)d_in[1];
    const float* emb       = (const float*)d_in[2];
    const float* W_ih_f    = (const float*)d_in[3];
    const float* W_hh_f    = (const float*)d_in[4];
    const float* b_f       = (const float*)d_in[5];
    const float* W_ih_b    = (const float*)d_in[6];
    const float* W_hh_b    = (const float*)d_in[7];
    const float* b_b       = (const float*)d_in[8];
    const float* W_lin     = (const float*)d_in[9];
    const float* b_lin     = (const float*)d_in[10];
    const float* trans     = (const float*)d_in[11];
    float* out = (float*)d_out;

    int smem_ip = (HID * NB + HID * IP_ROWS) * 4;                      // 148800 B
    int smem_rc = (HID * 152 + HID * RBS + 2 * 2432) * 4;              // 211456 B
    cudaFuncSetAttribute(k_inproj, cudaFuncAttributeMaxDynamicSharedMemorySize, smem_ip);
    cudaFuncSetAttribute(k_recur,  cudaFuncAttributeMaxDynamicSharedMemorySize, smem_rc);

    k_reset<<<1, 32>>>();
    k_gather<<<SEQ, 256>>>(sentences, emb);
    dim3 gip(IP_MB, SEQ, 2);
    k_inproj<<<gip, IP_THREADS, smem_ip>>>(W_ih_f, b_f, W_ih_b, b_b);
    k_recur<<<2 * RBG * RUS, R_THREADS, smem_rc>>>(W_hh_f, W_hh_b);
    k_emit<<<SEQ, 256>>>(W_lin, b_lin);
    k_crf<<<NB, 32>>>(tags, trans, out);
}